// round 6
// baseline (speedup 1.0000x reference)
#include <cuda_runtime.h>
#include <cuda_bf16.h>
#include <math.h>

// ---------------------------------------------------------------------------
// Problem constants
// ---------------------------------------------------------------------------
#define SEQ      4096
#define HIDDEN   2048
#define NHEADS   8
#define NKVHEADS 4
#define HDIM     256
#define CHUNK    2048   // CHUNK_START == 2048, CHUNK_END == 4096
#define QDIM     (NHEADS * HDIM)    // 2048
#define KVDIM    (NKVHEADS * HDIM)  // 1024

// Scratch (device globals — no allocation allowed)
__device__ float g_q [CHUNK * QDIM];     // 16 MB
__device__ float g_k [SEQ * KVDIM];      // 16 MB
__device__ float g_v [SEQ * KVDIM];      // 16 MB
__device__ float g_ao[CHUNK * QDIM];     // 16 MB

// ---------------------------------------------------------------------------
// SGEMM: C[M,N] = A[M,K] @ B[K,N], row-major, all dims multiples of tile sizes
// 128x128 block tile, BK=8, 256 threads, 8x8 micro-tile per thread.
// ---------------------------------------------------------------------------
__global__ __launch_bounds__(256) void sgemm128(
    const float* __restrict__ A, const float* __restrict__ B,
    float* __restrict__ C, int M, int N, int K)
{
    __shared__ float As[8][132];  // transposed A tile: As[k][m]
    __shared__ float Bs[8][132];  // Bs[k][n]

    const int bm = blockIdx.y * 128;
    const int bn = blockIdx.x * 128;
    const int t  = threadIdx.x;
    const int tx = t & 15;   // 0..15  (cols)
    const int ty = t >> 4;   // 0..15  (rows)

    // global load assignments
    const int arow = t >> 1;          // 0..127
    const int acol = (t & 1) * 4;     // 0 or 4
    const int brow = t >> 5;          // 0..7
    const int bcol = (t & 31) * 4;    // 0..124

    float4 acc[2][4][2];              // [rowGrp i][row ii][colGrp j], cols as float4
    #pragma unroll
    for (int i = 0; i < 2; i++)
        #pragma unroll
        for (int ii = 0; ii < 4; ii++)
            #pragma unroll
            for (int j = 0; j < 2; j++)
                acc[i][ii][j] = make_float4(0.f, 0.f, 0.f, 0.f);

    for (int k0 = 0; k0 < K; k0 += 8) {
        float4 av = *(const float4*)&A[(size_t)(bm + arow) * K + k0 + acol];
        float4 bv = *(const float4*)&B[(size_t)(k0 + brow) * N + bn + bcol];
        __syncthreads();
        As[acol + 0][arow] = av.x;
        As[acol + 1][arow] = av.y;
        As[acol + 2][arow] = av.z;
        As[acol + 3][arow] = av.w;
        *(float4*)&Bs[brow][bcol] = bv;
        __syncthreads();

        #pragma unroll
        for (int kk = 0; kk < 8; kk++) {
            float4 a0 = *(float4*)&As[kk][ty * 4];
            float4 a1 = *(float4*)&As[kk][ty * 4 + 64];
            float4 b0 = *(float4*)&Bs[kk][tx * 4];
            float4 b1 = *(float4*)&Bs[kk][tx * 4 + 64];
            float ar[2][4] = {{a0.x, a0.y, a0.z, a0.w}, {a1.x, a1.y, a1.z, a1.w}};
            float4 br[2] = {b0, b1};
            #pragma unroll
            for (int i = 0; i < 2; i++)
                #pragma unroll
                for (int ii = 0; ii < 4; ii++)
                    #pragma unroll
                    for (int j = 0; j < 2; j++) {
                        acc[i][ii][j].x += ar[i][ii] * br[j].x;
                        acc[i][ii][j].y += ar[i][ii] * br[j].y;
                        acc[i][ii][j].z += ar[i][ii] * br[j].z;
                        acc[i][ii][j].w += ar[i][ii] * br[j].w;
                    }
        }
    }

    #pragma unroll
    for (int i = 0; i < 2; i++)
        #pragma unroll
        for (int ii = 0; ii < 4; ii++) {
            int row = bm + ty * 4 + 64 * i + ii;
            #pragma unroll
            for (int j = 0; j < 2; j++)
                *(float4*)&C[(size_t)row * N + bn + tx * 4 + 64 * j] = acc[i][ii][j];
        }
}

// ---------------------------------------------------------------------------
// Fused RMSNorm (+ optional RoPE) over head_dim=256, in place.
// buf layout: (ntokens, nheads*256). block = 128 threads, grid = (ntokens, nheads)
// ---------------------------------------------------------------------------
__global__ __launch_bounds__(128) void norm_rope(
    float* __restrict__ buf, const float* __restrict__ w,
    const float* __restrict__ cosb, const float* __restrict__ sinb,
    int nheads, int pos_off, int use_rope)
{
    const int tok = blockIdx.x;
    const int h   = blockIdx.y;
    float* x = buf + ((size_t)tok * nheads + h) * HDIM;
    const int i = threadIdx.x;           // 0..127

    float x1 = x[i];
    float x2 = x[i + 128];
    float ss = x1 * x1 + x2 * x2;

    // reduce over 128 threads
    #pragma unroll
    for (int off = 16; off > 0; off >>= 1)
        ss += __shfl_xor_sync(0xffffffffu, ss, off);
    __shared__ float wsum[4];
    if ((i & 31) == 0) wsum[i >> 5] = ss;
    __syncthreads();
    float tot = wsum[0] + wsum[1] + wsum[2] + wsum[3];

    float scale = rsqrtf(tot * (1.0f / 256.0f) + 1e-6f);
    float xn1 = x1 * scale * (1.0f + w[i]);
    float xn2 = x2 * scale * (1.0f + w[i + 128]);

    if (use_rope) {
        const size_t p = (size_t)(pos_off + tok) * HDIM;
        float c1 = cosb[p + i],       s1 = sinb[p + i];
        float c2 = cosb[p + i + 128], s2 = sinb[p + i + 128];
        x[i]       = xn1 * c1 - xn2 * s1;   // rotate_half: [:h] gets -x[h:]
        x[i + 128] = xn2 * c2 + xn1 * s2;
    } else {
        x[i]       = xn1;
        x[i + 128] = xn2;
    }
}

// ---------------------------------------------------------------------------
// Flash attention (fp32). BQ=64 q rows, BK=64 k rows, d=256. 256 threads.
// grid = (CHUNK/64, NHEADS). Online softmax, softcap tanh, causal mask.
// K and V share one smem buffer (sequenced by barriers).
// ---------------------------------------------------------------------------
#define FA_KVS 260   // padded row stride for K/V tiles (conflict-free float4 reads)
#define FA_SS  65    // padded row stride for score tile

__global__ __launch_bounds__(256) void flash_attn(
    const float* __restrict__ Qg, const float* __restrict__ Kg,
    const float* __restrict__ Vg, float* __restrict__ Og)
{
    const int qt  = blockIdx.x;
    const int h   = blockIdx.y;
    const int q0  = qt * 64;
    const int kvh = h >> 1;

    extern __shared__ float sm[];
    float* Qs  = sm;                       // 64 * 256
    float* KVs = Qs + 64 * 256;            // 64 * FA_KVS
    float* Ss  = KVs + 64 * FA_KVS;        // 64 * FA_SS
    float* Ms  = Ss + 64 * FA_SS;          // 64
    float* Ls  = Ms + 64;                  // 64
    float* Cs  = Ls + 64;                  // 64

    const int t  = threadIdx.x;
    const int tx = t & 15;
    const int ty = t >> 4;
    const int warp = t >> 5;
    const int lane = t & 31;

    // load Q tile (rows q0..q0+63, head h)
    for (int i = t; i < 64 * 64; i += 256) {
        int r = i >> 6, c4 = i & 63;
        *(float4*)&Qs[r * 256 + c4 * 4] =
            *(const float4*)&Qg[(size_t)(q0 + r) * QDIM + h * HDIM + c4 * 4];
    }
    if (t < 64) { Ms[t] = -1e30f; Ls[t] = 0.f; }

    float4 o[4][4];   // rows ty*4+i, col groups n = 4*(tx+16*j)
    #pragma unroll
    for (int i = 0; i < 4; i++)
        #pragma unroll
        for (int j = 0; j < 4; j++)
            o[i][j] = make_float4(0.f, 0.f, 0.f, 0.f);

    const int qmax = CHUNK + q0 + 63;           // largest global q position in tile
    const int ntiles = (qmax + 1 + 63) >> 6;    // k tiles needed (<= 64)

    for (int kt = 0; kt < ntiles; kt++) {
        const int k0 = kt * 64;
        __syncthreads();   // protect KVs (V reads of prev iter) + Ss (PV reads)

        // load K tile
        for (int i = t; i < 64 * 64; i += 256) {
            int r = i >> 6, c4 = i & 63;
            *(float4*)&KVs[r * FA_KVS + c4 * 4] =
                *(const float4*)&Kg[(size_t)(k0 + r) * KVDIM + kvh * HDIM + c4 * 4];
        }
        __syncthreads();

        // S = Q @ K^T  (raw dot products)
        float s[4][4];
        #pragma unroll
        for (int i = 0; i < 4; i++)
            #pragma unroll
            for (int j = 0; j < 4; j++) s[i][j] = 0.f;

        for (int kd = 0; kd < 256; kd += 4) {
            float4 aq[4], bk[4];
            #pragma unroll
            for (int i = 0; i < 4; i++)
                aq[i] = *(float4*)&Qs[(ty * 4 + i) * 256 + kd];
            #pragma unroll
            for (int j = 0; j < 4; j++)
                bk[j] = *(float4*)&KVs[(tx + 16 * j) * FA_KVS + kd];
            #pragma unroll
            for (int i = 0; i < 4; i++)
                #pragma unroll
                for (int j = 0; j < 4; j++) {
                    s[i][j] += aq[i].x * bk[j].x;
                    s[i][j] += aq[i].y * bk[j].y;
                    s[i][j] += aq[i].z * bk[j].z;
                    s[i][j] += aq[i].w * bk[j].w;
                }
        }
        #pragma unroll
        for (int i = 0; i < 4; i++)
            #pragma unroll
            for (int j = 0; j < 4; j++)
                Ss[(ty * 4 + i) * FA_SS + tx + 16 * j] = s[i][j];
        __syncthreads();

        // load V tile (K no longer needed) — overlaps with softmax below
        for (int i = t; i < 64 * 64; i += 256) {
            int r = i >> 6, c4 = i & 63;
            *(float4*)&KVs[r * FA_KVS + c4 * 4] =
                *(const float4*)&Vg[(size_t)(k0 + r) * KVDIM + kvh * HDIM + c4 * 4];
        }

        // softmax update: warp w owns rows w*8 .. w*8+7
        #pragma unroll
        for (int rr = 0; rr < 8; rr++) {
            const int r = warp * 8 + rr;
            const int qpos = CHUNK + q0 + r;
            float v0 = Ss[r * FA_SS + lane];
            float v1 = Ss[r * FA_SS + lane + 32];
            // logits*scale -> softcap: 50*tanh(l/50); combined: 50*tanh(s*0.0625/50)
            float e0 = 50.f * tanhf(v0 * (0.0625f / 50.f));
            float e1 = 50.f * tanhf(v1 * (0.0625f / 50.f));
            bool m0 = (k0 + lane)      <= qpos;
            bool m1 = (k0 + lane + 32) <= qpos;
            float x0 = m0 ? e0 : -1e30f;
            float x1 = m1 ? e1 : -1e30f;
            float mx = fmaxf(x0, x1);
            #pragma unroll
            for (int off = 16; off > 0; off >>= 1)
                mx = fmaxf(mx, __shfl_xor_sync(0xffffffffu, mx, off));
            float mprev = Ms[r];
            float mnew  = fmaxf(mprev, mx);
            float p0 = m0 ? __expf(x0 - mnew) : 0.f;
            float p1 = m1 ? __expf(x1 - mnew) : 0.f;
            float sum = p0 + p1;
            #pragma unroll
            for (int off = 16; off > 0; off >>= 1)
                sum += __shfl_xor_sync(0xffffffffu, sum, off);
            if (lane == 0) {
                float corr = __expf(mprev - mnew);
                Cs[r] = corr;
                Ls[r] = Ls[r] * corr + sum;
                Ms[r] = mnew;
            }
            Ss[r * FA_SS + lane]      = p0;
            Ss[r * FA_SS + lane + 32] = p1;
        }
        __syncthreads();

        // rescale O accumulators
        float corr[4];
        #pragma unroll
        for (int i = 0; i < 4; i++) corr[i] = Cs[ty * 4 + i];
        #pragma unroll
        for (int i = 0; i < 4; i++)
            #pragma unroll
            for (int j = 0; j < 4; j++) {
                o[i][j].x *= corr[i]; o[i][j].y *= corr[i];
                o[i][j].z *= corr[i]; o[i][j].w *= corr[i];
            }

        // O += P @ V
        for (int k = 0; k < 64; k++) {
            float p[4];
            #pragma unroll
            for (int i = 0; i < 4; i++) p[i] = Ss[(ty * 4 + i) * FA_SS + k];
            float4 v[4];
            #pragma unroll
            for (int j = 0; j < 4; j++)
                v[j] = *(float4*)&KVs[k * FA_KVS + 4 * (tx + 16 * j)];
            #pragma unroll
            for (int i = 0; i < 4; i++)
                #pragma unroll
                for (int j = 0; j < 4; j++) {
                    o[i][j].x += p[i] * v[j].x;
                    o[i][j].y += p[i] * v[j].y;
                    o[i][j].z += p[i] * v[j].z;
                    o[i][j].w += p[i] * v[j].w;
                }
        }
    }

    // epilogue: O / l, write to attn-out buffer (token, head*256+d)
    #pragma unroll
    for (int i = 0; i < 4; i++) {
        float linv = 1.f / Ls[ty * 4 + i];
        int row = q0 + ty * 4 + i;
        #pragma unroll
        for (int j = 0; j < 4; j++) {
            float4 w4 = o[i][j];
            w4.x *= linv; w4.y *= linv; w4.z *= linv; w4.w *= linv;
            *(float4*)&Og[(size_t)row * QDIM + h * HDIM + 4 * (tx + 16 * j)] = w4;
        }
    }
}

// ---------------------------------------------------------------------------
// Launch
// ---------------------------------------------------------------------------
extern "C" void kernel_launch(void* const* d_in, const int* in_sizes, int n_in,
                              void* d_out, int out_size)
{
    const float* X    = (const float*)d_in[0];  // (1, 4096, 2048)
    const float* cosb = (const float*)d_in[1];  // (1, 4096, 256)
    const float* sinb = (const float*)d_in[2];  // (1, 4096, 256)
    // d_in[3] = attention_mask (causal; computed analytically instead)
    const float* wq   = (const float*)d_in[4];  // (2048, 2048)
    const float* wk   = (const float*)d_in[5];  // (2048, 1024)
    const float* wv   = (const float*)d_in[6];  // (2048, 1024)
    const float* wo   = (const float*)d_in[7];  // (2048, 2048)
    const float* qn   = (const float*)d_in[8];
    const float* kn   = (const float*)d_in[9];
    const float* vn   = (const float*)d_in[10];
    float* out = (float*)d_out;

    float *qb, *kb, *vb, *ab;
    cudaGetSymbolAddress((void**)&qb, g_q);
    cudaGetSymbolAddress((void**)&kb, g_k);
    cudaGetSymbolAddress((void**)&vb, g_v);
    cudaGetSymbolAddress((void**)&ab, g_ao);

    // Projections
    sgemm128<<<dim3(QDIM / 128, CHUNK / 128), 256>>>(X + (size_t)CHUNK * HIDDEN, wq, qb,
                                                     CHUNK, QDIM, HIDDEN);
    sgemm128<<<dim3(KVDIM / 128, SEQ / 128), 256>>>(X, wk, kb, SEQ, KVDIM, HIDDEN);
    sgemm128<<<dim3(KVDIM / 128, SEQ / 128), 256>>>(X, wv, vb, SEQ, KVDIM, HIDDEN);

    // RMSNorm (+RoPE for Q/K)
    norm_rope<<<dim3(CHUNK, NHEADS), 128>>>(qb, qn, cosb, sinb, NHEADS, CHUNK, 1);
    norm_rope<<<dim3(SEQ, NKVHEADS), 128>>>(kb, kn, cosb, sinb, NKVHEADS, 0, 1);
    norm_rope<<<dim3(SEQ, NKVHEADS), 128>>>(vb, vn, cosb, sinb, NKVHEADS, 0, 0);

    // Flash attention
    const size_t smem = (64 * 256 + 64 * FA_KVS + 64 * FA_SS + 3 * 64) * sizeof(float);
    cudaFuncSetAttribute(flash_attn, cudaFuncAttributeMaxDynamicSharedMemorySize, (int)smem);
    flash_attn<<<dim3(CHUNK / 64, NHEADS), 256, smem>>>(qb, kb, vb, ab);

    // Output projection
    sgemm128<<<dim3(HIDDEN / 128, CHUNK / 128), 256>>>(ab, wo, out, CHUNK, HIDDEN, QDIM);
}

// round 9
// speedup vs baseline: 3.6605x; 3.6605x over previous
#include <cuda_runtime.h>
#include <cuda_bf16.h>
#include <cstdint>
#include <math.h>

// ---------------------------------------------------------------------------
// Problem constants
// ---------------------------------------------------------------------------
#define SEQ      4096
#define HIDDEN   2048
#define NHEADS   8
#define NKVHEADS 4
#define HDIM     256
#define CHUNK    2048
#define QDIM     (NHEADS * HDIM)    // 2048
#define KVDIM    (NKVHEADS * HDIM)  // 1024

// ---------------------------------------------------------------------------
// Scratch (device globals — no allocation allowed)
// ---------------------------------------------------------------------------
__device__ float g_x  [SEQ * HIDDEN];
__device__ float g_q  [CHUNK * QDIM];
__device__ float g_k  [SEQ * KVDIM];
__device__ float g_v  [SEQ * KVDIM];
__device__ float g_ao [CHUNK * QDIM];
__device__ float g_wqT[HIDDEN * QDIM];
__device__ float g_wkT[HIDDEN * KVDIM];
__device__ float g_wvT[HIDDEN * KVDIM];
__device__ float g_woT[QDIM * HIDDEN];
__device__ float g_vT [NKVHEADS * HDIM * SEQ];
__device__ float g_S  [NHEADS * CHUNK * SEQ];   // 256 MB

// ---------------------------------------------------------------------------
// PTX helpers (all sm_80+-portable; NO arch-specific 'a' features)
// ---------------------------------------------------------------------------
static __device__ __forceinline__ uint32_t s2u(const void* p) {
    uint32_t a;
    asm("{ .reg .u64 t; cvta.to.shared.u64 t, %1; cvt.u32.u64 %0, t; }"
        : "=r"(a) : "l"(p));
    return a;
}

static __device__ __forceinline__ void cp16(uint32_t dst, const void* src) {
    asm volatile("cp.async.cg.shared.global [%0], [%1], 16;"
                 :: "r"(dst), "l"(src) : "memory");
}
#define CP_COMMIT() asm volatile("cp.async.commit_group;" ::: "memory")
#define CP_WAIT1()  asm volatile("cp.async.wait_group 1;" ::: "memory")

// round-to-nearest tf32 (zeros low 13 mantissa bits, unbiased)
static __device__ __forceinline__ float rtf32(float x) {
    uint32_t u = __float_as_uint(x), o;
    asm("cvt.rna.tf32.f32 %0, %1;" : "=r"(o) : "r"(u));
    return __uint_as_float(o);
}

// ---------------------------------------------------------------------------
// tf32 mma.sync GEMM: C[M,N] = A[M,K](K-major,lda) @ B[N,K](K-major,ldb)^T
// CTA tile 128x128, BK=32, 3-stage cp.async pipeline, 256 threads (8 warps,
// 2x4 warp grid, 64x32 per warp, m16n8k8 fragments).
// ncap: skip CTA if bn >= ncap0 + by*ncapSlope   (causal tile skip for S)
// kcap: truncate K at kcap0 + by*kcapSlope       (PV truncation)
// ---------------------------------------------------------------------------
#define TM 128
#define TN 128
#define TK 32
#define LDSW 36                       // padded row stride (floats): banks (4g+t4)%32
#define OPFL (128 * LDSW)             // floats per operand tile
#define STGFL (2 * OPFL)              // floats per stage
#define GEMM_SMEM (3 * STGFL * 4)     // 110592 bytes

__global__ __launch_bounds__(256) void gemm_tf32(
    const float* __restrict__ A, const float* __restrict__ B,
    float* __restrict__ C,
    int K, int lda, int ldb, int ldc,
    long long sAz, long long sBz, long long sCz, int bzShift,
    int ncap0, int ncapSlope, int kcap0, int kcapSlope, int roundC)
{
    const int bm = blockIdx.y * TM;
    const int bn = blockIdx.x * TN;
    const int z  = blockIdx.z;
    if (bn >= ncap0 + (int)blockIdx.y * ncapSlope) return;

    long long kcl = (long long)kcap0 + (long long)blockIdx.y * kcapSlope;
    const int Keff = (kcl < (long long)K) ? (int)kcl : K;
    const int kt = Keff / TK;

    A += (size_t)z * sAz + (size_t)bm * lda;
    B += (size_t)(z >> bzShift) * sBz + (size_t)bn * ldb;
    C += (size_t)z * sCz;

    extern __shared__ float smf[];
    const int tid  = threadIdx.x;
    const int w    = tid >> 5, lane = tid & 31;
    const int wm   = w >> 2,   wn   = w & 3;     // 2 x 4 warp grid
    const int g    = lane >> 2, t4  = lane & 3;

    // per-thread load coords: 1024 16B-chunks per operand, 4 per thread
    const int lr = tid >> 3;            // base row (0..31), +32*i
    const int lc = (tid & 7) * 4;       // k offset in floats

    float acc[4][4][4];
    #pragma unroll
    for (int a1 = 0; a1 < 4; a1++)
        #pragma unroll
        for (int b1 = 0; b1 < 4; b1++)
            #pragma unroll
            for (int c1 = 0; c1 < 4; c1++) acc[a1][b1][c1] = 0.f;

    // ---- stage loader ----
    #define LOAD_STAGE(st, k0)                                                  \
    do {                                                                        \
        float* dA = smf + (st) * STGFL;                                         \
        float* dB = dA + OPFL;                                                  \
        _Pragma("unroll")                                                       \
        for (int i = 0; i < 4; i++) {                                           \
            int row = lr + i * 32;                                              \
            cp16(s2u(dA + row * LDSW + lc), A + (size_t)row * lda + (k0) + lc); \
            cp16(s2u(dB + row * LDSW + lc), B + (size_t)row * ldb + (k0) + lc); \
        }                                                                       \
        CP_COMMIT();                                                            \
    } while (0)

    // prologue: 2 groups always committed (empty group if kt==1; kt>=8 here)
    LOAD_STAGE(0, 0);
    if (kt > 1) LOAD_STAGE(1, TK); else CP_COMMIT();

    for (int it = 0; it < kt; it++) {
        CP_WAIT1();            // all but most-recent group complete -> stage it ready
        __syncthreads();

        const int st = it % 3;
        const float* sA = smf + st * STGFL;
        const float* sB = sA + OPFL;

        // prefetch stage it+2 (buffer (it+2)%3 == (it-1)%3, free after the sync)
        if (it + 2 < kt) { const int s2 = (it + 2) % 3; LOAD_STAGE(s2, (it + 2) * TK); }
        else CP_COMMIT();

        #pragma unroll
        for (int kk = 0; kk < 4; kk++) {
            uint32_t af[4][4], bf[4][2];
            #pragma unroll
            for (int tm = 0; tm < 4; tm++) {
                const float* p = sA + (wm * 64 + tm * 16 + g) * LDSW + kk * 8 + t4;
                af[tm][0] = __float_as_uint(p[0]);
                af[tm][1] = __float_as_uint(p[8 * LDSW]);
                af[tm][2] = __float_as_uint(p[4]);
                af[tm][3] = __float_as_uint(p[8 * LDSW + 4]);
            }
            #pragma unroll
            for (int tn = 0; tn < 4; tn++) {
                const float* p = sB + (wn * 32 + tn * 8 + g) * LDSW + kk * 8 + t4;
                bf[tn][0] = __float_as_uint(p[0]);
                bf[tn][1] = __float_as_uint(p[4]);
            }
            #pragma unroll
            for (int tm = 0; tm < 4; tm++)
                #pragma unroll
                for (int tn = 0; tn < 4; tn++)
                    asm volatile(
                        "mma.sync.aligned.m16n8k8.row.col.f32.tf32.tf32.f32 "
                        "{%0,%1,%2,%3}, {%4,%5,%6,%7}, {%8,%9}, {%0,%1,%2,%3};"
                        : "+f"(acc[tm][tn][0]), "+f"(acc[tm][tn][1]),
                          "+f"(acc[tm][tn][2]), "+f"(acc[tm][tn][3])
                        : "r"(af[tm][0]), "r"(af[tm][1]),
                          "r"(af[tm][2]), "r"(af[tm][3]),
                          "r"(bf[tn][0]), "r"(bf[tn][1]));
        }
    }

    // epilogue: c0,c1 at (row,2t4), c2,c3 at (row+8,2t4)
    #pragma unroll
    for (int tm = 0; tm < 4; tm++) {
        const int row0 = bm + wm * 64 + tm * 16 + g;
        #pragma unroll
        for (int tn = 0; tn < 4; tn++) {
            const int col = bn + wn * 32 + tn * 8 + 2 * t4;
            float2 v0 = make_float2(acc[tm][tn][0], acc[tm][tn][1]);
            float2 v1 = make_float2(acc[tm][tn][2], acc[tm][tn][3]);
            if (roundC) {
                v0.x = rtf32(v0.x); v0.y = rtf32(v0.y);
                v1.x = rtf32(v1.x); v1.y = rtf32(v1.y);
            }
            *(float2*)&C[(size_t)row0 * ldc + col]       = v0;
            *(float2*)&C[(size_t)(row0 + 8) * ldc + col] = v1;
        }
    }
    #undef LOAD_STAGE
}

// ---------------------------------------------------------------------------
// 32x32 tiled transpose with tf32 rounding: out[c][r] = rtf32(in[r][c])
// ---------------------------------------------------------------------------
__global__ __launch_bounds__(256) void transposeK(
    const float* __restrict__ in, float* __restrict__ out,
    int ldin, int ldout, long long sInZ, long long sOutZ)
{
    __shared__ float t[32][33];
    const int z = blockIdx.z;
    in  += (size_t)z * sInZ;
    out += (size_t)z * sOutZ;
    const int c0 = blockIdx.x * 32, r0 = blockIdx.y * 32;
    const int tx = threadIdx.x, ty = threadIdx.y;
    #pragma unroll
    for (int i = ty; i < 32; i += 8)
        t[i][tx] = in[(size_t)(r0 + i) * ldin + c0 + tx];
    __syncthreads();
    #pragma unroll
    for (int i = ty; i < 32; i += 8)
        out[(size_t)(c0 + i) * ldout + r0 + tx] = rtf32(t[tx][i]);
}

// ---------------------------------------------------------------------------
// Elementwise tf32 round (X -> g_x)
// ---------------------------------------------------------------------------
__global__ __launch_bounds__(256) void round_x(
    const float4* __restrict__ in, float4* __restrict__ out)
{
    int i = blockIdx.x * 256 + threadIdx.x;
    float4 v = in[i];
    v.x = rtf32(v.x); v.y = rtf32(v.y); v.z = rtf32(v.z); v.w = rtf32(v.w);
    out[i] = v;
}

// ---------------------------------------------------------------------------
// RMSNorm (+ optional RoPE), head_dim = 256, in place, tf32-rounded output.
// ---------------------------------------------------------------------------
__global__ __launch_bounds__(128) void norm_rope(
    float* __restrict__ buf, const float* __restrict__ w,
    const float* __restrict__ cosb, const float* __restrict__ sinb,
    int nheads, int pos_off, int use_rope)
{
    const int tok = blockIdx.x;
    const int h   = blockIdx.y;
    float* x = buf + ((size_t)tok * nheads + h) * HDIM;
    const int i = threadIdx.x;

    float x1 = x[i];
    float x2 = x[i + 128];
    float ss = x1 * x1 + x2 * x2;
    #pragma unroll
    for (int off = 16; off > 0; off >>= 1)
        ss += __shfl_xor_sync(0xffffffffu, ss, off);
    __shared__ float wsum[4];
    if ((i & 31) == 0) wsum[i >> 5] = ss;
    __syncthreads();
    float tot = wsum[0] + wsum[1] + wsum[2] + wsum[3];

    float scale = rsqrtf(tot * (1.0f / 256.0f) + 1e-6f);
    float xn1 = x1 * scale * (1.0f + w[i]);
    float xn2 = x2 * scale * (1.0f + w[i + 128]);

    if (use_rope) {
        const size_t p = (size_t)(pos_off + tok) * HDIM;
        float c1 = cosb[p + i],       s1 = sinb[p + i];
        float c2 = cosb[p + i + 128], s2 = sinb[p + i + 128];
        x[i]       = rtf32(xn1 * c1 - xn2 * s1);
        x[i + 128] = rtf32(xn2 * c2 + xn1 * s2);
    } else {
        x[i]       = rtf32(xn1);
        x[i + 128] = rtf32(xn2);
    }
}

// ---------------------------------------------------------------------------
// Softcap + causal mask + softmax over each S row (4096 wide), in place.
// Skips 1024-col chunks fully past the diagonal; masked entries -> exact 0.
// ---------------------------------------------------------------------------
__global__ __launch_bounds__(256) void softmax_cap(float* __restrict__ S)
{
    const int r = blockIdx.x, h = blockIdx.y;
    float* row = S + ((size_t)h * CHUNK + r) * SEQ;
    const int qpos  = CHUNK + r;
    const int lastc = qpos >> 10;
    const int t = threadIdx.x;
    const int lane = t & 31, w = t >> 5;

    float v[16];
    float mx = -1e30f;
    #pragma unroll
    for (int p = 0; p < 4; p++) {
        if (p > lastc) continue;
        int col = p * 1024 + t * 4;
        float4 x = *(float4*)(row + col);
        float xa[4] = {x.x, x.y, x.z, x.w};
        #pragma unroll
        for (int q2 = 0; q2 < 4; q2++) {
            float l = 50.f * tanhf(xa[q2] * (0.0625f / 50.f));
            l = (col + q2 <= qpos) ? l : -1e30f;   // mask BEFORE max (garbage-safe)
            v[p * 4 + q2] = l;
            mx = fmaxf(mx, l);
        }
    }
    __shared__ float rmax[8], rsum[8];
    #pragma unroll
    for (int o = 16; o; o >>= 1) mx = fmaxf(mx, __shfl_xor_sync(~0u, mx, o));
    if (!lane) rmax[w] = mx;
    __syncthreads();
    mx = rmax[0];
    #pragma unroll
    for (int i = 1; i < 8; i++) mx = fmaxf(mx, rmax[i]);

    float sum = 0.f;
    #pragma unroll
    for (int p = 0; p < 4; p++) {
        if (p > lastc) continue;
        #pragma unroll
        for (int q2 = 0; q2 < 4; q2++) {
            float e = __expf(v[p * 4 + q2] - mx);
            v[p * 4 + q2] = e;
            sum += e;
        }
    }
    #pragma unroll
    for (int o = 16; o; o >>= 1) sum += __shfl_xor_sync(~0u, sum, o);
    if (!lane) rsum[w] = sum;
    __syncthreads();
    sum = 0.f;
    #pragma unroll
    for (int i = 0; i < 8; i++) sum += rsum[i];
    const float inv = 1.f / sum;

    #pragma unroll
    for (int p = 0; p < 4; p++) {
        if (p > lastc) continue;
        int col = p * 1024 + t * 4;
        float4 o4;
        o4.x = rtf32(v[p * 4 + 0] * inv);
        o4.y = rtf32(v[p * 4 + 1] * inv);
        o4.z = rtf32(v[p * 4 + 2] * inv);
        o4.w = rtf32(v[p * 4 + 3] * inv);
        *(float4*)(row + col) = o4;
    }
}

// ---------------------------------------------------------------------------
// Launch
// ---------------------------------------------------------------------------
extern "C" void kernel_launch(void* const* d_in, const int* in_sizes, int n_in,
                              void* d_out, int out_size)
{
    const float* X    = (const float*)d_in[0];
    const float* cosb = (const float*)d_in[1];
    const float* sinb = (const float*)d_in[2];
    const float* wq   = (const float*)d_in[4];
    const float* wk   = (const float*)d_in[5];
    const float* wv   = (const float*)d_in[6];
    const float* wo   = (const float*)d_in[7];
    const float* qn   = (const float*)d_in[8];
    const float* kn   = (const float*)d_in[9];
    const float* vn   = (const float*)d_in[10];
    float* out = (float*)d_out;

    float *xb, *qb, *kb, *vb, *ab, *wqT, *wkT, *wvT, *woT, *vT, *Sb;
    cudaGetSymbolAddress((void**)&xb,  g_x);
    cudaGetSymbolAddress((void**)&qb,  g_q);
    cudaGetSymbolAddress((void**)&kb,  g_k);
    cudaGetSymbolAddress((void**)&vb,  g_v);
    cudaGetSymbolAddress((void**)&ab,  g_ao);
    cudaGetSymbolAddress((void**)&wqT, g_wqT);
    cudaGetSymbolAddress((void**)&wkT, g_wkT);
    cudaGetSymbolAddress((void**)&wvT, g_wvT);
    cudaGetSymbolAddress((void**)&woT, g_woT);
    cudaGetSymbolAddress((void**)&vT,  g_vT);
    cudaGetSymbolAddress((void**)&Sb,  g_S);

    cudaFuncSetAttribute(gemm_tf32, cudaFuncAttributeMaxDynamicSharedMemorySize,
                         GEMM_SMEM);

    const int BIG = 1 << 30;
    dim3 tb(32, 8);

    // tf32-round inputs
    round_x<<<SEQ * HIDDEN / 1024, 256>>>((const float4*)X, (float4*)xb);
    transposeK<<<dim3(QDIM / 32,  HIDDEN / 32), tb>>>(wq, wqT, QDIM,  HIDDEN, 0, 0);
    transposeK<<<dim3(KVDIM / 32, HIDDEN / 32), tb>>>(wk, wkT, KVDIM, HIDDEN, 0, 0);
    transposeK<<<dim3(KVDIM / 32, HIDDEN / 32), tb>>>(wv, wvT, KVDIM, HIDDEN, 0, 0);
    transposeK<<<dim3(HIDDEN / 32, QDIM / 32),  tb>>>(wo, woT, HIDDEN, QDIM,  0, 0);

    // projections
    gemm_tf32<<<dim3(QDIM / TN, CHUNK / TM, 1), 256, GEMM_SMEM>>>(
        xb + (size_t)CHUNK * HIDDEN, wqT, qb,
        HIDDEN, HIDDEN, HIDDEN, QDIM, 0, 0, 0, 0, BIG, 0, BIG, 0, 0);
    gemm_tf32<<<dim3(KVDIM / TN, SEQ / TM, 1), 256, GEMM_SMEM>>>(
        xb, wkT, kb, HIDDEN, HIDDEN, HIDDEN, KVDIM, 0, 0, 0, 0, BIG, 0, BIG, 0, 0);
    gemm_tf32<<<dim3(KVDIM / TN, SEQ / TM, 1), 256, GEMM_SMEM>>>(
        xb, wvT, vb, HIDDEN, HIDDEN, HIDDEN, KVDIM, 0, 0, 0, 0, BIG, 0, BIG, 0, 0);

    // RMSNorm (+RoPE), outputs tf32-rounded
    norm_rope<<<dim3(CHUNK, NHEADS), 128>>>(qb, qn, cosb, sinb, NHEADS, CHUNK, 1);
    norm_rope<<<dim3(SEQ, NKVHEADS), 128>>>(kb, kn, cosb, sinb, NKVHEADS, 0, 1);
    norm_rope<<<dim3(SEQ, NKVHEADS), 128>>>(vb, vn, cosb, sinb, NKVHEADS, 0, 0);

    // V^T per kv head: [256, 4096]
    transposeK<<<dim3(HDIM / 32, SEQ / 32, NKVHEADS), tb>>>(
        vb, vT, KVDIM, SEQ, HDIM, (long long)HDIM * SEQ);

    // S = Q @ K^T  (batched over 8 heads, causal tile skip)
    gemm_tf32<<<dim3(SEQ / TN, CHUNK / TM, NHEADS), 256, GEMM_SMEM>>>(
        qb, kb, Sb,
        HDIM, QDIM, KVDIM, SEQ,
        (long long)HDIM, (long long)HDIM, (long long)CHUNK * SEQ, 1,
        CHUNK + TM, TM, BIG, 0, 0);

    // softcap + mask + softmax (writes P, tf32-rounded, zeros in masked region)
    softmax_cap<<<dim3(CHUNK, NHEADS), 256>>>(Sb);

    // O = P @ V  (K truncated per M-tile: Keff = CHUNK + TM*(by+1))
    gemm_tf32<<<dim3(HDIM / TN, CHUNK / TM, NHEADS), 256, GEMM_SMEM>>>(
        Sb, vT, ab,
        SEQ, SEQ, SEQ, QDIM,
        (long long)CHUNK * SEQ, (long long)HDIM * SEQ, (long long)HDIM, 1,
        BIG, 0, CHUNK + TM, TM, 1);

    // output projection
    gemm_tf32<<<dim3(HIDDEN / TN, CHUNK / TM, 1), 256, GEMM_SMEM>>>(
        ab, woT, out, QDIM, QDIM, QDIM, HIDDEN, 0, 0, 0, 0, BIG, 0, BIG, 0, 0);
}

// round 12
// speedup vs baseline: 3.7910x; 1.0356x over previous
#include <cuda_runtime.h>
#include <cuda_bf16.h>
#include <cstdint>
#include <math.h>

// ---------------------------------------------------------------------------
// Problem constants
// ---------------------------------------------------------------------------
#define SEQ      4096
#define HIDDEN   2048
#define NHEADS   8
#define NKVHEADS 4
#define HDIM     256
#define CHUNK    2048
#define QDIM     (NHEADS * HDIM)    // 2048
#define KVDIM    (NKVHEADS * HDIM)  // 1024

// ---------------------------------------------------------------------------
// Scratch (device globals — no allocation allowed)
// ---------------------------------------------------------------------------
__device__ float g_x  [SEQ * HIDDEN];
__device__ float g_q  [CHUNK * QDIM];
__device__ float g_k  [SEQ * KVDIM];
__device__ float g_v  [SEQ * KVDIM];
__device__ float g_ao [CHUNK * QDIM];
__device__ float g_wqT[HIDDEN * QDIM];
__device__ float g_wkT[HIDDEN * KVDIM];
__device__ float g_wvT[HIDDEN * KVDIM];
__device__ float g_woT[QDIM * HIDDEN];
__device__ float g_vT [NKVHEADS * HDIM * SEQ];
__device__ float g_S  [NHEADS * CHUNK * SEQ];   // 256 MB

// ---------------------------------------------------------------------------
// PTX helpers (sm_80+-portable only — the harness compiles PTX for plain
// sm_103, so tcgen05/TMEM are unavailable; mma.sync is the tensor path)
// ---------------------------------------------------------------------------
static __device__ __forceinline__ uint32_t s2u(const void* p) {
    uint32_t a;
    asm("{ .reg .u64 t; cvta.to.shared.u64 t, %1; cvt.u32.u64 %0, t; }"
        : "=r"(a) : "l"(p));
    return a;
}

static __device__ __forceinline__ void cp16(uint32_t dst, const void* src) {
    asm volatile("cp.async.cg.shared.global [%0], [%1], 16;"
                 :: "r"(dst), "l"(src) : "memory");
}
#define CP_COMMIT() asm volatile("cp.async.commit_group;" ::: "memory")
#define CP_WAIT1()  asm volatile("cp.async.wait_group 1;" ::: "memory")

// round-to-nearest tf32 (zeros low 13 mantissa bits, unbiased)
static __device__ __forceinline__ float rtf32(float x) {
    uint32_t u = __float_as_uint(x), o;
    asm("cvt.rna.tf32.f32 %0, %1;" : "=r"(o) : "r"(u));
    return __uint_as_float(o);
}

// ---------------------------------------------------------------------------
// tf32 mma.sync GEMM: C[M,N] = A[M,K](K-major,lda) @ B[N,K](K-major,ldb)^T
// CTA tile 128x256, BK=32, 3-stage cp.async pipeline, 256 threads
// (8 warps, 2x4 grid, 64x64 per warp, m16n8k8 fragments, 32 MMA/k8-step).
// ncap: skip CTA if bn >= ncap0 + by*ncapSlope   (causal tile skip for S)
// kcap: truncate K at kcap0 + by*kcapSlope       (PV truncation)
// ---------------------------------------------------------------------------
#define TM 128
#define TN 256
#define TK 32
#define LDSW 36                       // padded row stride (floats): conflict-free
#define AFL  (128 * LDSW)             // A-tile floats
#define BFL  (256 * LDSW)             // B-tile floats
#define STGFL (AFL + BFL)             // floats per stage = 13824
#define GEMM_SMEM (3 * STGFL * 4)     // 165888 bytes

__global__ __launch_bounds__(256) void gemm_tf32(
    const float* __restrict__ A, const float* __restrict__ B,
    float* __restrict__ C,
    int K, int lda, int ldb, int ldc,
    long long sAz, long long sBz, long long sCz, int bzShift,
    int ncap0, int ncapSlope, int kcap0, int kcapSlope, int roundC)
{
    const int bm = blockIdx.y * TM;
    const int bn = blockIdx.x * TN;
    const int z  = blockIdx.z;
    if (bn >= ncap0 + (int)blockIdx.y * ncapSlope) return;

    long long kcl = (long long)kcap0 + (long long)blockIdx.y * kcapSlope;
    const int Keff = (kcl < (long long)K) ? (int)kcl : K;
    const int kt = Keff / TK;

    A += (size_t)z * sAz + (size_t)bm * lda;
    B += (size_t)(z >> bzShift) * sBz + (size_t)bn * ldb;
    C += (size_t)z * sCz;

    extern __shared__ float smf[];
    const int tid  = threadIdx.x;
    const int w    = tid >> 5, lane = tid & 31;
    const int wm   = w >> 2,   wn   = w & 3;     // 2 x 4 warp grid
    const int g    = lane >> 2, t4  = lane & 3;

    // per-thread load coords (16B chunks): A = 1024 chunks (4/thr), B = 2048 (8/thr)
    const int lr = tid >> 3;            // base row (0..31), step 32
    const int lc = (tid & 7) * 4;       // k offset in floats

    float acc[4][8][4];
    #pragma unroll
    for (int a1 = 0; a1 < 4; a1++)
        #pragma unroll
        for (int b1 = 0; b1 < 8; b1++)
            #pragma unroll
            for (int c1 = 0; c1 < 4; c1++) acc[a1][b1][c1] = 0.f;

    #define LOAD_STAGE(st, k0)                                                  \
    do {                                                                        \
        float* dA = smf + (st) * STGFL;                                         \
        float* dB = dA + AFL;                                                   \
        _Pragma("unroll")                                                       \
        for (int i = 0; i < 4; i++) {                                           \
            int row = lr + i * 32;                                              \
            cp16(s2u(dA + row * LDSW + lc), A + (size_t)row * lda + (k0) + lc); \
        }                                                                       \
        _Pragma("unroll")                                                       \
        for (int i = 0; i < 8; i++) {                                           \
            int row = lr + i * 32;                                              \
            cp16(s2u(dB + row * LDSW + lc), B + (size_t)row * ldb + (k0) + lc); \
        }                                                                       \
        CP_COMMIT();                                                            \
    } while (0)

    LOAD_STAGE(0, 0);
    if (kt > 1) LOAD_STAGE(1, TK); else CP_COMMIT();

    for (int it = 0; it < kt; it++) {
        CP_WAIT1();
        __syncthreads();

        const int st = it % 3;
        const float* sA = smf + st * STGFL;
        const float* sB = sA + AFL;

        if (it + 2 < kt) { const int s2 = (it + 2) % 3; LOAD_STAGE(s2, (it + 2) * TK); }
        else CP_COMMIT();

        #pragma unroll
        for (int kk = 0; kk < 4; kk++) {
            uint32_t af[4][4], bf[8][2];
            #pragma unroll
            for (int tm = 0; tm < 4; tm++) {
                const float* p = sA + (wm * 64 + tm * 16 + g) * LDSW + kk * 8 + t4;
                af[tm][0] = __float_as_uint(p[0]);
                af[tm][1] = __float_as_uint(p[8 * LDSW]);
                af[tm][2] = __float_as_uint(p[4]);
                af[tm][3] = __float_as_uint(p[8 * LDSW + 4]);
            }
            #pragma unroll
            for (int tn = 0; tn < 8; tn++) {
                const float* p = sB + (wn * 64 + tn * 8 + g) * LDSW + kk * 8 + t4;
                bf[tn][0] = __float_as_uint(p[0]);
                bf[tn][1] = __float_as_uint(p[4]);
            }
            #pragma unroll
            for (int tm = 0; tm < 4; tm++)
                #pragma unroll
                for (int tn = 0; tn < 8; tn++)
                    asm volatile(
                        "mma.sync.aligned.m16n8k8.row.col.f32.tf32.tf32.f32 "
                        "{%0,%1,%2,%3}, {%4,%5,%6,%7}, {%8,%9}, {%0,%1,%2,%3};"
                        : "+f"(acc[tm][tn][0]), "+f"(acc[tm][tn][1]),
                          "+f"(acc[tm][tn][2]), "+f"(acc[tm][tn][3])
                        : "r"(af[tm][0]), "r"(af[tm][1]),
                          "r"(af[tm][2]), "r"(af[tm][3]),
                          "r"(bf[tn][0]), "r"(bf[tn][1]));
        }
    }

    // epilogue: c0,c1 at (row,2t4), c2,c3 at (row+8,2t4)
    #pragma unroll
    for (int tm = 0; tm < 4; tm++) {
        const int row0 = bm + wm * 64 + tm * 16 + g;
        #pragma unroll
        for (int tn = 0; tn < 8; tn++) {
            const int col = bn + wn * 64 + tn * 8 + 2 * t4;
            float2 v0 = make_float2(acc[tm][tn][0], acc[tm][tn][1]);
            float2 v1 = make_float2(acc[tm][tn][2], acc[tm][tn][3]);
            if (roundC) {
                v0.x = rtf32(v0.x); v0.y = rtf32(v0.y);
                v1.x = rtf32(v1.x); v1.y = rtf32(v1.y);
            }
            *(float2*)&C[(size_t)row0 * ldc + col]       = v0;
            *(float2*)&C[(size_t)(row0 + 8) * ldc + col] = v1;
        }
    }
    #undef LOAD_STAGE
}

// ---------------------------------------------------------------------------
// 32x32 tiled transpose with tf32 rounding: out[c][r] = rtf32(in[r][c])
// ---------------------------------------------------------------------------
__global__ __launch_bounds__(256) void transposeK(
    const float* __restrict__ in, float* __restrict__ out,
    int ldin, int ldout, long long sInZ, long long sOutZ)
{
    __shared__ float t[32][33];
    const int z = blockIdx.z;
    in  += (size_t)z * sInZ;
    out += (size_t)z * sOutZ;
    const int c0 = blockIdx.x * 32, r0 = blockIdx.y * 32;
    const int tx = threadIdx.x, ty = threadIdx.y;
    #pragma unroll
    for (int i = ty; i < 32; i += 8)
        t[i][tx] = in[(size_t)(r0 + i) * ldin + c0 + tx];
    __syncthreads();
    #pragma unroll
    for (int i = ty; i < 32; i += 8)
        out[(size_t)(c0 + i) * ldout + r0 + tx] = rtf32(t[tx][i]);
}

// ---------------------------------------------------------------------------
// Elementwise tf32 round (X -> g_x)
// ---------------------------------------------------------------------------
__global__ __launch_bounds__(256) void round_x(
    const float4* __restrict__ in, float4* __restrict__ out)
{
    int i = blockIdx.x * 256 + threadIdx.x;
    float4 v = in[i];
    v.x = rtf32(v.x); v.y = rtf32(v.y); v.z = rtf32(v.z); v.w = rtf32(v.w);
    out[i] = v;
}

// ---------------------------------------------------------------------------
// RMSNorm (+ optional RoPE), head_dim = 256, in place, tf32-rounded output.
// ---------------------------------------------------------------------------
__global__ __launch_bounds__(128) void norm_rope(
    float* __restrict__ buf, const float* __restrict__ w,
    const float* __restrict__ cosb, const float* __restrict__ sinb,
    int nheads, int pos_off, int use_rope)
{
    const int tok = blockIdx.x;
    const int h   = blockIdx.y;
    float* x = buf + ((size_t)tok * nheads + h) * HDIM;
    const int i = threadIdx.x;

    float x1 = x[i];
    float x2 = x[i + 128];
    float ss = x1 * x1 + x2 * x2;
    #pragma unroll
    for (int off = 16; off > 0; off >>= 1)
        ss += __shfl_xor_sync(0xffffffffu, ss, off);
    __shared__ float wsum[4];
    if ((i & 31) == 0) wsum[i >> 5] = ss;
    __syncthreads();
    float tot = wsum[0] + wsum[1] + wsum[2] + wsum[3];

    float scale = rsqrtf(tot * (1.0f / 256.0f) + 1e-6f);
    float xn1 = x1 * scale * (1.0f + w[i]);
    float xn2 = x2 * scale * (1.0f + w[i + 128]);

    if (use_rope) {
        const size_t p = (size_t)(pos_off + tok) * HDIM;
        float c1 = cosb[p + i],       s1 = sinb[p + i];
        float c2 = cosb[p + i + 128], s2 = sinb[p + i + 128];
        x[i]       = rtf32(xn1 * c1 - xn2 * s1);
        x[i + 128] = rtf32(xn2 * c2 + xn1 * s2);
    } else {
        x[i]       = rtf32(xn1);
        x[i + 128] = rtf32(xn2);
    }
}

// ---------------------------------------------------------------------------
// Softcap + causal mask + softmax over each S row (4096 wide), in place.
// Skips 1024-col chunks fully past the diagonal; masked entries -> exact 0.
// ---------------------------------------------------------------------------
__global__ __launch_bounds__(256) void softmax_cap(float* __restrict__ S)
{
    const int r = blockIdx.x, h = blockIdx.y;
    float* row = S + ((size_t)h * CHUNK + r) * SEQ;
    const int qpos  = CHUNK + r;
    const int lastc = qpos >> 10;
    const int t = threadIdx.x;
    const int lane = t & 31, w = t >> 5;

    float v[16];
    float mx = -1e30f;
    #pragma unroll
    for (int p = 0; p < 4; p++) {
        if (p > lastc) continue;
        int col = p * 1024 + t * 4;
        float4 x = *(float4*)(row + col);
        float xa[4] = {x.x, x.y, x.z, x.w};
        #pragma unroll
        for (int q2 = 0; q2 < 4; q2++) {
            float l = 50.f * tanhf(xa[q2] * (0.0625f / 50.f));
            l = (col + q2 <= qpos) ? l : -1e30f;   // mask BEFORE max (garbage-safe)
            v[p * 4 + q2] = l;
            mx = fmaxf(mx, l);
        }
    }
    __shared__ float rmax[8], rsum[8];
    #pragma unroll
    for (int o = 16; o; o >>= 1) mx = fmaxf(mx, __shfl_xor_sync(~0u, mx, o));
    if (!lane) rmax[w] = mx;
    __syncthreads();
    mx = rmax[0];
    #pragma unroll
    for (int i = 1; i < 8; i++) mx = fmaxf(mx, rmax[i]);

    float sum = 0.f;
    #pragma unroll
    for (int p = 0; p < 4; p++) {
        if (p > lastc) continue;
        #pragma unroll
        for (int q2 = 0; q2 < 4; q2++) {
            float e = __expf(v[p * 4 + q2] - mx);
            v[p * 4 + q2] = e;
            sum += e;
        }
    }
    #pragma unroll
    for (int o = 16; o; o >>= 1) sum += __shfl_xor_sync(~0u, sum, o);
    if (!lane) rsum[w] = sum;
    __syncthreads();
    sum = 0.f;
    #pragma unroll
    for (int i = 0; i < 8; i++) sum += rsum[i];
    const float inv = 1.f / sum;

    #pragma unroll
    for (int p = 0; p < 4; p++) {
        if (p > lastc) continue;
        int col = p * 1024 + t * 4;
        float4 o4;
        o4.x = rtf32(v[p * 4 + 0] * inv);
        o4.y = rtf32(v[p * 4 + 1] * inv);
        o4.z = rtf32(v[p * 4 + 2] * inv);
        o4.w = rtf32(v[p * 4 + 3] * inv);
        *(float4*)(row + col) = o4;
    }
}

// ---------------------------------------------------------------------------
// Launch
// ---------------------------------------------------------------------------
extern "C" void kernel_launch(void* const* d_in, const int* in_sizes, int n_in,
                              void* d_out, int out_size)
{
    const float* X    = (const float*)d_in[0];
    const float* cosb = (const float*)d_in[1];
    const float* sinb = (const float*)d_in[2];
    const float* wq   = (const float*)d_in[4];
    const float* wk   = (const float*)d_in[5];
    const float* wv   = (const float*)d_in[6];
    const float* wo   = (const float*)d_in[7];
    const float* qn   = (const float*)d_in[8];
    const float* kn   = (const float*)d_in[9];
    const float* vn   = (const float*)d_in[10];
    float* out = (float*)d_out;

    float *xb, *qb, *kb, *vb, *ab, *wqT, *wkT, *wvT, *woT, *vT, *Sb;
    cudaGetSymbolAddress((void**)&xb,  g_x);
    cudaGetSymbolAddress((void**)&qb,  g_q);
    cudaGetSymbolAddress((void**)&kb,  g_k);
    cudaGetSymbolAddress((void**)&vb,  g_v);
    cudaGetSymbolAddress((void**)&ab,  g_ao);
    cudaGetSymbolAddress((void**)&wqT, g_wqT);
    cudaGetSymbolAddress((void**)&wkT, g_wkT);
    cudaGetSymbolAddress((void**)&wvT, g_wvT);
    cudaGetSymbolAddress((void**)&woT, g_woT);
    cudaGetSymbolAddress((void**)&vT,  g_vT);
    cudaGetSymbolAddress((void**)&Sb,  g_S);

    cudaFuncSetAttribute(gemm_tf32, cudaFuncAttributeMaxDynamicSharedMemorySize,
                         GEMM_SMEM);

    const int BIG = 1 << 30;
    dim3 tb(32, 8);

    // tf32-round inputs
    round_x<<<SEQ * HIDDEN / 1024, 256>>>((const float4*)X, (float4*)xb);
    transposeK<<<dim3(QDIM / 32,  HIDDEN / 32), tb>>>(wq, wqT, QDIM,  HIDDEN, 0, 0);
    transposeK<<<dim3(KVDIM / 32, HIDDEN / 32), tb>>>(wk, wkT, KVDIM, HIDDEN, 0, 0);
    transposeK<<<dim3(KVDIM / 32, HIDDEN / 32), tb>>>(wv, wvT, KVDIM, HIDDEN, 0, 0);
    transposeK<<<dim3(HIDDEN / 32, QDIM / 32),  tb>>>(wo, woT, HIDDEN, QDIM,  0, 0);

    // projections (all single-wave 128-CTA grids now)
    gemm_tf32<<<dim3(QDIM / TN, CHUNK / TM, 1), 256, GEMM_SMEM>>>(
        xb + (size_t)CHUNK * HIDDEN, wqT, qb,
        HIDDEN, HIDDEN, HIDDEN, QDIM, 0, 0, 0, 0, BIG, 0, BIG, 0, 0);
    gemm_tf32<<<dim3(KVDIM / TN, SEQ / TM, 1), 256, GEMM_SMEM>>>(
        xb, wkT, kb, HIDDEN, HIDDEN, HIDDEN, KVDIM, 0, 0, 0, 0, BIG, 0, BIG, 0, 0);
    gemm_tf32<<<dim3(KVDIM / TN, SEQ / TM, 1), 256, GEMM_SMEM>>>(
        xb, wvT, vb, HIDDEN, HIDDEN, HIDDEN, KVDIM, 0, 0, 0, 0, BIG, 0, BIG, 0, 0);

    // RMSNorm (+RoPE), outputs tf32-rounded
    norm_rope<<<dim3(CHUNK, NHEADS), 128>>>(qb, qn, cosb, sinb, NHEADS, CHUNK, 1);
    norm_rope<<<dim3(SEQ, NKVHEADS), 128>>>(kb, kn, cosb, sinb, NKVHEADS, 0, 1);
    norm_rope<<<dim3(SEQ, NKVHEADS), 128>>>(vb, vn, cosb, sinb, NKVHEADS, 0, 0);

    // V^T per kv head: [256, 4096]
    transposeK<<<dim3(HDIM / 32, SEQ / 32, NKVHEADS), tb>>>(
        vb, vT, KVDIM, SEQ, HDIM, (long long)HDIM * SEQ);

    // S = Q @ K^T  (batched over 8 heads, causal tile skip)
    gemm_tf32<<<dim3(SEQ / TN, CHUNK / TM, NHEADS), 256, GEMM_SMEM>>>(
        qb, kb, Sb,
        HDIM, QDIM, KVDIM, SEQ,
        (long long)HDIM, (long long)HDIM, (long long)CHUNK * SEQ, 1,
        CHUNK + TM, TM, BIG, 0, 0);

    // softcap + mask + softmax (writes P, tf32-rounded, zeros in masked region)
    softmax_cap<<<dim3(CHUNK, NHEADS), 256>>>(Sb);

    // O = P @ V  (K truncated per M-tile: Keff = CHUNK + TM*(by+1))
    gemm_tf32<<<dim3(HDIM / TN, CHUNK / TM, NHEADS), 256, GEMM_SMEM>>>(
        Sb, vT, ab,
        SEQ, SEQ, SEQ, QDIM,
        (long long)CHUNK * SEQ, (long long)HDIM * SEQ, (long long)HDIM, 1,
        BIG, 0, CHUNK + TM, TM, 1);

    // output projection
    gemm_tf32<<<dim3(HIDDEN / TN, CHUNK / TM, 1), 256, GEMM_SMEM>>>(
        ab, woT, out, QDIM, QDIM, QDIM, HIDDEN, 0, 0, 0, 0, BIG, 0, BIG, 0, 0);
}